// round 2
// baseline (speedup 1.0000x reference)
#include <cuda_runtime.h>
#include <cstdint>

#define N_NODES 50000
#define N_EDGES 800000
#define D_IN    256
#define D_OUT   128
#define EPSV    1e-9f

// Scratch (allocation-free rule: __device__ globals)
__device__ float g_Z [(size_t)N_NODES * D_OUT];   // Z = feat @ W1   [N, 128]
__device__ int   g_cnt[N_NODES];                  // per-row edge counts
__device__ int   g_rs [N_NODES + 1];              // CSR row starts
__device__ int   g_cur[N_NODES];                  // scatter cursors
__device__ int   g_scol[N_EDGES];                 // sorted cols
__device__ float g_sval[N_EDGES];                 // sorted vals

// ---------------- packed f32x2 helpers (Blackwell) ----------------
__device__ __forceinline__ unsigned long long pack2(float v) {
    unsigned long long r;
    asm("mov.b64 %0, {%1, %2};" : "=l"(r) : "f"(v), "f"(v));
    return r;
}
__device__ __forceinline__ void unpack2(unsigned long long v, float& lo, float& hi) {
    asm("mov.b64 {%0, %1}, %2;" : "=f"(lo), "=f"(hi) : "l"(v));
}
__device__ __forceinline__ void fma2(unsigned long long& d, unsigned long long a, unsigned long long b) {
    asm("fma.rn.f32x2 %0, %1, %2, %0;" : "+l"(d) : "l"(a), "l"(b));
}

// ---------------- CSR build ----------------
__global__ void zero_cnt_kernel() {
    int i = blockIdx.x * blockDim.x + threadIdx.x;
    if (i < N_NODES) g_cnt[i] = 0;
}

__global__ void hist_kernel(const int* __restrict__ erow) {
    int e = blockIdx.x * blockDim.x + threadIdx.x;
    if (e < N_EDGES) atomicAdd(&g_cnt[__ldg(erow + e)], 1);
}

// single-block exclusive scan over 50k counts -> g_rs, g_cur
__global__ void __launch_bounds__(1024) scan_kernel() {
    __shared__ int sums[1024];
    const int CH = (N_NODES + 1023) / 1024;  // 49
    int t = threadIdx.x;
    int base = t * CH;
    int s = 0;
    for (int i = 0; i < CH; ++i) {
        int idx = base + i;
        if (idx < N_NODES) s += g_cnt[idx];
    }
    sums[t] = s;
    __syncthreads();
    // Hillis-Steele inclusive scan
    for (int off = 1; off < 1024; off <<= 1) {
        int v = (t >= off) ? sums[t - off] : 0;
        __syncthreads();
        sums[t] += v;
        __syncthreads();
    }
    int run = sums[t] - s;   // exclusive prefix
    for (int i = 0; i < CH; ++i) {
        int idx = base + i;
        if (idx < N_NODES) {
            g_rs[idx]  = run;
            g_cur[idx] = run;
            run += g_cnt[idx];
        }
    }
    if (t == 1023) g_rs[N_NODES] = sums[1023];
}

__global__ void scatter_kernel(const int* __restrict__ erow, const int* __restrict__ ecol,
                               const float* __restrict__ eval) {
    int e = blockIdx.x * blockDim.x + threadIdx.x;
    if (e >= N_EDGES) return;
    int r = __ldg(erow + e);
    int pos = atomicAdd(&g_cur[r], 1);
    g_scol[pos] = __ldg(ecol + e);
    g_sval[pos] = __ldg(eval + e);
}

// ---------------- fused GEMM: out[:, :128] = LN(relu(feat@W0+b0)); g_Z = feat@W1 ----------------
#define TM 64
#define KC 64
#define XSTRIDE 68
#define GEMM_SMEM ((KC*256 + TM*XSTRIDE) * 4)   // 82944 B

__global__ void __launch_bounds__(256, 2)
gemm_fused_kernel(const float* __restrict__ feat,
                  const float* __restrict__ W0, const float* __restrict__ b0,
                  const float* __restrict__ scale0, const float* __restrict__ offset0,
                  const float* __restrict__ W1,
                  float* __restrict__ out)
{
    extern __shared__ float smem[];
    float* Ws = smem;                 // [KC][256]
    float* Xs = smem + KC * 256;      // [TM][XSTRIDE]

    const int tid  = threadIdx.x;
    const int warp = tid >> 5;
    const int lane = tid & 31;
    const int row0 = blockIdx.x * TM;

    unsigned long long acc[8][4];
#pragma unroll
    for (int r = 0; r < 8; ++r)
#pragma unroll
        for (int j = 0; j < 4; ++j) acc[r][j] = 0ull;

    for (int kc = 0; kc < D_IN / KC; ++kc) {
        for (int i = tid; i < (KC * 256) / 4; i += 256) {
            int k  = i >> 6;
            int n4 = (i & 63) * 4;
            int kg = kc * KC + k;
            float4 v;
            if (n4 < 128) v = *reinterpret_cast<const float4*>(W0 + (size_t)kg * 128 + n4);
            else          v = *reinterpret_cast<const float4*>(W1 + (size_t)kg * 128 + (n4 - 128));
            *reinterpret_cast<float4*>(&Ws[k * 256 + n4]) = v;
        }
        for (int i = tid; i < (TM * KC) / 4; i += 256) {
            int r  = i >> 4;
            int c4 = (i & 15) * 4;
            int grow = row0 + r;
            float4 v = make_float4(0.f, 0.f, 0.f, 0.f);
            if (grow < N_NODES)
                v = *reinterpret_cast<const float4*>(feat + (size_t)grow * D_IN + kc * KC + c4);
            *reinterpret_cast<float4*>(&Xs[r * XSTRIDE + c4]) = v;
        }
        __syncthreads();

        const float* xbase = Xs + (warp * 8) * XSTRIDE;
#pragma unroll 4
        for (int k = 0; k < KC; ++k) {
            const float* wrow = Ws + k * 256;
            unsigned long long w0 = *reinterpret_cast<const unsigned long long*>(wrow + 2 * lane);
            unsigned long long w1 = *reinterpret_cast<const unsigned long long*>(wrow + 64 + 2 * lane);
            unsigned long long w2 = *reinterpret_cast<const unsigned long long*>(wrow + 128 + 2 * lane);
            unsigned long long w3 = *reinterpret_cast<const unsigned long long*>(wrow + 192 + 2 * lane);
#pragma unroll
            for (int rr = 0; rr < 8; ++rr) {
                unsigned long long x2 = pack2(xbase[rr * XSTRIDE + k]);
                fma2(acc[rr][0], x2, w0);
                fma2(acc[rr][1], x2, w1);
                fma2(acc[rr][2], x2, w2);
                fma2(acc[rr][3], x2, w3);
            }
        }
        __syncthreads();
    }

    float2 bA = *reinterpret_cast<const float2*>(b0 + 2 * lane);
    float2 bB = *reinterpret_cast<const float2*>(b0 + 64 + 2 * lane);
    float2 sA = *reinterpret_cast<const float2*>(scale0 + 2 * lane);
    float2 sB = *reinterpret_cast<const float2*>(scale0 + 64 + 2 * lane);
    float2 oA = *reinterpret_cast<const float2*>(offset0 + 2 * lane);
    float2 oB = *reinterpret_cast<const float2*>(offset0 + 64 + 2 * lane);

#pragma unroll
    for (int rr = 0; rr < 8; ++rr) {
        int row = row0 + warp * 8 + rr;
        float a0, a1, a2, a3;
        unpack2(acc[rr][0], a0, a1);
        unpack2(acc[rr][1], a2, a3);
        a0 = fmaxf(a0 + bA.x, 0.f);
        a1 = fmaxf(a1 + bA.y, 0.f);
        a2 = fmaxf(a2 + bB.x, 0.f);
        a3 = fmaxf(a3 + bB.y, 0.f);
        float s = a0 + a1 + a2 + a3;
        float q = a0 * a0 + a1 * a1 + a2 * a2 + a3 * a3;
#pragma unroll
        for (int off = 16; off > 0; off >>= 1) {
            s += __shfl_xor_sync(0xffffffffu, s, off);
            q += __shfl_xor_sync(0xffffffffu, q, off);
        }
        float mean = s * (1.f / 128.f);
        float var  = q * (1.f / 128.f) - mean * mean;
        float inv  = rsqrtf(var + EPSV);
        if (row < N_NODES) {
            float2 w;
            w.x = (a0 - mean) * inv * sA.x + oA.x;
            w.y = (a1 - mean) * inv * sA.y + oA.y;
            *reinterpret_cast<float2*>(out + (size_t)row * 256 + 2 * lane) = w;
            w.x = (a2 - mean) * inv * sB.x + oB.x;
            w.y = (a3 - mean) * inv * sB.y + oB.y;
            *reinterpret_cast<float2*>(out + (size_t)row * 256 + 64 + 2 * lane) = w;
            *reinterpret_cast<unsigned long long*>(g_Z + (size_t)row * 128 + 2 * lane) = acc[rr][2];
            *reinterpret_cast<unsigned long long*>(g_Z + (size_t)row * 128 + 64 + 2 * lane) = acc[rr][3];
        }
    }
}

// ---------------- fused CSR SpMM + LN: out[:, 128:] = LN(relu((A@Z) + b1)) ----------------
// One warp per row; per-lane float4 accumulator (lane covers cols 4l..4l+3).
__global__ void __launch_bounds__(256)
spmm_ln_kernel(const float* __restrict__ b1, const float* __restrict__ scale1,
               const float* __restrict__ offset1, float* __restrict__ out)
{
    int row = blockIdx.x * 8 + (threadIdx.x >> 5);
    if (row >= N_NODES) return;
    int lane = threadIdx.x & 31;

    int start = __ldg(&g_rs[row]);
    int end   = __ldg(&g_rs[row + 1]);

    float4 acc = make_float4(0.f, 0.f, 0.f, 0.f);
    int e = start;
    for (; e + 1 < end; e += 2) {
        int   c0 = __ldg(g_scol + e);
        int   c1 = __ldg(g_scol + e + 1);
        float v0 = __ldg(g_sval + e);
        float v1 = __ldg(g_sval + e + 1);
        float4 z0 = *reinterpret_cast<const float4*>(g_Z + (size_t)c0 * 128 + lane * 4);
        float4 z1 = *reinterpret_cast<const float4*>(g_Z + (size_t)c1 * 128 + lane * 4);
        acc.x = fmaf(v0, z0.x, acc.x); acc.y = fmaf(v0, z0.y, acc.y);
        acc.z = fmaf(v0, z0.z, acc.z); acc.w = fmaf(v0, z0.w, acc.w);
        acc.x = fmaf(v1, z1.x, acc.x); acc.y = fmaf(v1, z1.y, acc.y);
        acc.z = fmaf(v1, z1.z, acc.z); acc.w = fmaf(v1, z1.w, acc.w);
    }
    if (e < end) {
        int   c0 = __ldg(g_scol + e);
        float v0 = __ldg(g_sval + e);
        float4 z0 = *reinterpret_cast<const float4*>(g_Z + (size_t)c0 * 128 + lane * 4);
        acc.x = fmaf(v0, z0.x, acc.x); acc.y = fmaf(v0, z0.y, acc.y);
        acc.z = fmaf(v0, z0.z, acc.z); acc.w = fmaf(v0, z0.w, acc.w);
    }

    float4 b = *reinterpret_cast<const float4*>(b1 + lane * 4);
    acc.x = fmaxf(acc.x + b.x, 0.f);
    acc.y = fmaxf(acc.y + b.y, 0.f);
    acc.z = fmaxf(acc.z + b.z, 0.f);
    acc.w = fmaxf(acc.w + b.w, 0.f);
    float s = acc.x + acc.y + acc.z + acc.w;
    float q = acc.x * acc.x + acc.y * acc.y + acc.z * acc.z + acc.w * acc.w;
#pragma unroll
    for (int off = 16; off > 0; off >>= 1) {
        s += __shfl_xor_sync(0xffffffffu, s, off);
        q += __shfl_xor_sync(0xffffffffu, q, off);
    }
    float mean = s * (1.f / 128.f);
    float var  = q * (1.f / 128.f) - mean * mean;
    float inv  = rsqrtf(var + EPSV);
    float4 sc = *reinterpret_cast<const float4*>(scale1 + lane * 4);
    float4 of = *reinterpret_cast<const float4*>(offset1 + lane * 4);
    float4 w;
    w.x = (acc.x - mean) * inv * sc.x + of.x;
    w.y = (acc.y - mean) * inv * sc.y + of.y;
    w.z = (acc.z - mean) * inv * sc.z + of.z;
    w.w = (acc.w - mean) * inv * sc.w + of.w;
    *reinterpret_cast<float4*>(out + (size_t)row * 256 + 128 + lane * 4) = w;
}

extern "C" void kernel_launch(void* const* d_in, const int* in_sizes, int n_in,
                              void* d_out, int out_size)
{
    const float* feat    = (const float*)d_in[0];
    const float* W0      = (const float*)d_in[1];
    const float* b0      = (const float*)d_in[2];
    const float* scale0  = (const float*)d_in[3];
    const float* offset0 = (const float*)d_in[4];
    const float* W1      = (const float*)d_in[5];
    const float* b1      = (const float*)d_in[6];
    const float* scale1  = (const float*)d_in[7];
    const float* offset1 = (const float*)d_in[8];
    const int*   erow    = (const int*)d_in[9];
    const int*   ecol    = (const int*)d_in[10];
    const float* eval    = (const float*)d_in[11];
    float* out = (float*)d_out;

    cudaFuncSetAttribute(gemm_fused_kernel,
                         cudaFuncAttributeMaxDynamicSharedMemorySize, GEMM_SMEM);

    // CSR build (independent of GEMM)
    zero_cnt_kernel<<<(N_NODES + 255) / 256, 256>>>();
    hist_kernel<<<(N_EDGES + 255) / 256, 256>>>(erow);
    scan_kernel<<<1, 1024>>>();
    scatter_kernel<<<(N_EDGES + 255) / 256, 256>>>(erow, ecol, eval);

    // GEMMs (produces out[:, :128] and g_Z)
    gemm_fused_kernel<<<(N_NODES + TM - 1) / TM, 256, GEMM_SMEM>>>(
        feat, W0, b0, scale0, offset0, W1, out);

    // fused SpMM + LN (produces out[:, 128:])
    spmm_ln_kernel<<<(N_NODES + 7) / 8, 256>>>(b1, scale1, offset1, out);
}

// round 3
// speedup vs baseline: 1.0460x; 1.0460x over previous
#include <cuda_runtime.h>
#include <cstdint>

#define N_NODES 50000
#define N_EDGES 800000
#define D_IN    256
#define D_OUT   128
#define EPSV    1e-9f

// Scratch (allocation-free rule: __device__ globals)
__device__ float g_Z [(size_t)N_NODES * D_OUT];   // Z = feat @ W1   [N, 128]
__device__ int   g_cnt[N_NODES];                  // per-row edge counts
__device__ int   g_rs [N_NODES + 1];              // CSR row starts
__device__ int   g_cur[N_NODES];                  // scatter cursors
__device__ int   g_scol[N_EDGES];                 // sorted cols
__device__ float g_sval[N_EDGES];                 // sorted vals

// ---------------- packed f32x2 helpers (Blackwell) ----------------
__device__ __forceinline__ unsigned long long pack2(float v) {
    unsigned long long r;
    asm("mov.b64 %0, {%1, %2};" : "=l"(r) : "f"(v), "f"(v));
    return r;
}
__device__ __forceinline__ void unpack2(unsigned long long v, float& lo, float& hi) {
    asm("mov.b64 {%0, %1}, %2;" : "=f"(lo), "=f"(hi) : "l"(v));
}
__device__ __forceinline__ void fma2(unsigned long long& d, unsigned long long a, unsigned long long b) {
    asm("fma.rn.f32x2 %0, %1, %2, %0;" : "+l"(d) : "l"(a), "l"(b));
}

// ---------------- CSR build ----------------
__global__ void zero_cnt_kernel() {
    int i = blockIdx.x * blockDim.x + threadIdx.x;
    if (i < N_NODES) g_cnt[i] = 0;
}

__global__ void hist_kernel(const int* __restrict__ erow) {
    int e = blockIdx.x * blockDim.x + threadIdx.x;
    if (e < N_EDGES) atomicAdd(&g_cnt[__ldg(erow + e)], 1);
}

// single-block exclusive scan over 50k counts -> g_rs, g_cur
__global__ void __launch_bounds__(1024) scan_kernel() {
    __shared__ int sums[1024];
    const int CH = (N_NODES + 1023) / 1024;  // 49
    int t = threadIdx.x;
    int base = t * CH;
    int s = 0;
    for (int i = 0; i < CH; ++i) {
        int idx = base + i;
        if (idx < N_NODES) s += g_cnt[idx];
    }
    sums[t] = s;
    __syncthreads();
    // Hillis-Steele inclusive scan
    for (int off = 1; off < 1024; off <<= 1) {
        int v = (t >= off) ? sums[t - off] : 0;
        __syncthreads();
        sums[t] += v;
        __syncthreads();
    }
    int run = sums[t] - s;   // exclusive prefix
    for (int i = 0; i < CH; ++i) {
        int idx = base + i;
        if (idx < N_NODES) {
            g_rs[idx]  = run;
            g_cur[idx] = run;
            run += g_cnt[idx];
        }
    }
    if (t == 1023) g_rs[N_NODES] = sums[1023];
}

__global__ void scatter_kernel(const int* __restrict__ erow, const int* __restrict__ ecol,
                               const float* __restrict__ eval) {
    int e = blockIdx.x * blockDim.x + threadIdx.x;
    if (e >= N_EDGES) return;
    int r = __ldg(erow + e);
    int pos = atomicAdd(&g_cur[r], 1);
    g_scol[pos] = __ldg(ecol + e);
    g_sval[pos] = __ldg(eval + e);
}

// ---------------- fused GEMM: out[:, :128] = LN(relu(feat@W0+b0)); g_Z = feat@W1 ----------------
#define TM 64
#define KC 64
#define XSTRIDE 68
#define GEMM_SMEM ((KC*256 + TM*XSTRIDE) * 4)   // 82944 B

__global__ void __launch_bounds__(256, 2)
gemm_fused_kernel(const float* __restrict__ feat,
                  const float* __restrict__ W0, const float* __restrict__ b0,
                  const float* __restrict__ scale0, const float* __restrict__ offset0,
                  const float* __restrict__ W1,
                  float* __restrict__ out)
{
    extern __shared__ float smem[];
    float* Ws = smem;                 // [KC][256]
    float* Xs = smem + KC * 256;      // [TM][XSTRIDE]

    const int tid  = threadIdx.x;
    const int warp = tid >> 5;
    const int lane = tid & 31;
    const int row0 = blockIdx.x * TM;

    unsigned long long acc[8][4];
#pragma unroll
    for (int r = 0; r < 8; ++r)
#pragma unroll
        for (int j = 0; j < 4; ++j) acc[r][j] = 0ull;

    for (int kc = 0; kc < D_IN / KC; ++kc) {
        for (int i = tid; i < (KC * 256) / 4; i += 256) {
            int k  = i >> 6;
            int n4 = (i & 63) * 4;
            int kg = kc * KC + k;
            float4 v;
            if (n4 < 128) v = *reinterpret_cast<const float4*>(W0 + (size_t)kg * 128 + n4);
            else          v = *reinterpret_cast<const float4*>(W1 + (size_t)kg * 128 + (n4 - 128));
            *reinterpret_cast<float4*>(&Ws[k * 256 + n4]) = v;
        }
        for (int i = tid; i < (TM * KC) / 4; i += 256) {
            int r  = i >> 4;
            int c4 = (i & 15) * 4;
            int grow = row0 + r;
            float4 v = make_float4(0.f, 0.f, 0.f, 0.f);
            if (grow < N_NODES)
                v = *reinterpret_cast<const float4*>(feat + (size_t)grow * D_IN + kc * KC + c4);
            *reinterpret_cast<float4*>(&Xs[r * XSTRIDE + c4]) = v;
        }
        __syncthreads();

        const float* xbase = Xs + (warp * 8) * XSTRIDE;
#pragma unroll 4
        for (int k = 0; k < KC; ++k) {
            const float* wrow = Ws + k * 256;
            unsigned long long w0 = *reinterpret_cast<const unsigned long long*>(wrow + 2 * lane);
            unsigned long long w1 = *reinterpret_cast<const unsigned long long*>(wrow + 64 + 2 * lane);
            unsigned long long w2 = *reinterpret_cast<const unsigned long long*>(wrow + 128 + 2 * lane);
            unsigned long long w3 = *reinterpret_cast<const unsigned long long*>(wrow + 192 + 2 * lane);
#pragma unroll
            for (int rr = 0; rr < 8; ++rr) {
                unsigned long long x2 = pack2(xbase[rr * XSTRIDE + k]);
                fma2(acc[rr][0], x2, w0);
                fma2(acc[rr][1], x2, w1);
                fma2(acc[rr][2], x2, w2);
                fma2(acc[rr][3], x2, w3);
            }
        }
        __syncthreads();
    }

    float2 bA = *reinterpret_cast<const float2*>(b0 + 2 * lane);
    float2 bB = *reinterpret_cast<const float2*>(b0 + 64 + 2 * lane);
    float2 sA = *reinterpret_cast<const float2*>(scale0 + 2 * lane);
    float2 sB = *reinterpret_cast<const float2*>(scale0 + 64 + 2 * lane);
    float2 oA = *reinterpret_cast<const float2*>(offset0 + 2 * lane);
    float2 oB = *reinterpret_cast<const float2*>(offset0 + 64 + 2 * lane);

#pragma unroll
    for (int rr = 0; rr < 8; ++rr) {
        int row = row0 + warp * 8 + rr;
        float a0, a1, a2, a3;
        unpack2(acc[rr][0], a0, a1);
        unpack2(acc[rr][1], a2, a3);
        a0 = fmaxf(a0 + bA.x, 0.f);
        a1 = fmaxf(a1 + bA.y, 0.f);
        a2 = fmaxf(a2 + bB.x, 0.f);
        a3 = fmaxf(a3 + bB.y, 0.f);
        float s = a0 + a1 + a2 + a3;
        float q = a0 * a0 + a1 * a1 + a2 * a2 + a3 * a3;
#pragma unroll
        for (int off = 16; off > 0; off >>= 1) {
            s += __shfl_xor_sync(0xffffffffu, s, off);
            q += __shfl_xor_sync(0xffffffffu, q, off);
        }
        float mean = s * (1.f / 128.f);
        float var  = q * (1.f / 128.f) - mean * mean;
        float inv  = rsqrtf(var + EPSV);
        if (row < N_NODES) {
            float2 w;
            w.x = (a0 - mean) * inv * sA.x + oA.x;
            w.y = (a1 - mean) * inv * sA.y + oA.y;
            *reinterpret_cast<float2*>(out + (size_t)row * 256 + 2 * lane) = w;
            w.x = (a2 - mean) * inv * sB.x + oB.x;
            w.y = (a3 - mean) * inv * sB.y + oB.y;
            *reinterpret_cast<float2*>(out + (size_t)row * 256 + 64 + 2 * lane) = w;
            *reinterpret_cast<unsigned long long*>(g_Z + (size_t)row * 128 + 2 * lane) = acc[rr][2];
            *reinterpret_cast<unsigned long long*>(g_Z + (size_t)row * 128 + 64 + 2 * lane) = acc[rr][3];
        }
    }
}

// ---------------- fused CSR SpMM + LN: out[:, 128:] = LN(relu((A@Z) + b1)) ----------------
// One warp per row; per-lane float4 accumulator (lane covers cols 4l..4l+3).
__global__ void __launch_bounds__(256)
spmm_ln_kernel(const float* __restrict__ b1, const float* __restrict__ scale1,
               const float* __restrict__ offset1, float* __restrict__ out)
{
    int row = blockIdx.x * 8 + (threadIdx.x >> 5);
    if (row >= N_NODES) return;
    int lane = threadIdx.x & 31;

    int start = __ldg(&g_rs[row]);
    int end   = __ldg(&g_rs[row + 1]);

    float4 acc = make_float4(0.f, 0.f, 0.f, 0.f);
    int e = start;
    for (; e + 1 < end; e += 2) {
        int   c0 = __ldg(g_scol + e);
        int   c1 = __ldg(g_scol + e + 1);
        float v0 = __ldg(g_sval + e);
        float v1 = __ldg(g_sval + e + 1);
        float4 z0 = *reinterpret_cast<const float4*>(g_Z + (size_t)c0 * 128 + lane * 4);
        float4 z1 = *reinterpret_cast<const float4*>(g_Z + (size_t)c1 * 128 + lane * 4);
        acc.x = fmaf(v0, z0.x, acc.x); acc.y = fmaf(v0, z0.y, acc.y);
        acc.z = fmaf(v0, z0.z, acc.z); acc.w = fmaf(v0, z0.w, acc.w);
        acc.x = fmaf(v1, z1.x, acc.x); acc.y = fmaf(v1, z1.y, acc.y);
        acc.z = fmaf(v1, z1.z, acc.z); acc.w = fmaf(v1, z1.w, acc.w);
    }
    if (e < end) {
        int   c0 = __ldg(g_scol + e);
        float v0 = __ldg(g_sval + e);
        float4 z0 = *reinterpret_cast<const float4*>(g_Z + (size_t)c0 * 128 + lane * 4);
        acc.x = fmaf(v0, z0.x, acc.x); acc.y = fmaf(v0, z0.y, acc.y);
        acc.z = fmaf(v0, z0.z, acc.z); acc.w = fmaf(v0, z0.w, acc.w);
    }

    float4 b = *reinterpret_cast<const float4*>(b1 + lane * 4);
    acc.x = fmaxf(acc.x + b.x, 0.f);
    acc.y = fmaxf(acc.y + b.y, 0.f);
    acc.z = fmaxf(acc.z + b.z, 0.f);
    acc.w = fmaxf(acc.w + b.w, 0.f);
    float s = acc.x + acc.y + acc.z + acc.w;
    float q = acc.x * acc.x + acc.y * acc.y + acc.z * acc.z + acc.w * acc.w;
#pragma unroll
    for (int off = 16; off > 0; off >>= 1) {
        s += __shfl_xor_sync(0xffffffffu, s, off);
        q += __shfl_xor_sync(0xffffffffu, q, off);
    }
    float mean = s * (1.f / 128.f);
    float var  = q * (1.f / 128.f) - mean * mean;
    float inv  = rsqrtf(var + EPSV);
    float4 sc = *reinterpret_cast<const float4*>(scale1 + lane * 4);
    float4 of = *reinterpret_cast<const float4*>(offset1 + lane * 4);
    float4 w;
    w.x = (acc.x - mean) * inv * sc.x + of.x;
    w.y = (acc.y - mean) * inv * sc.y + of.y;
    w.z = (acc.z - mean) * inv * sc.z + of.z;
    w.w = (acc.w - mean) * inv * sc.w + of.w;
    *reinterpret_cast<float4*>(out + (size_t)row * 256 + 128 + lane * 4) = w;
}

extern "C" void kernel_launch(void* const* d_in, const int* in_sizes, int n_in,
                              void* d_out, int out_size)
{
    const float* feat    = (const float*)d_in[0];
    const float* W0      = (const float*)d_in[1];
    const float* b0      = (const float*)d_in[2];
    const float* scale0  = (const float*)d_in[3];
    const float* offset0 = (const float*)d_in[4];
    const float* W1      = (const float*)d_in[5];
    const float* b1      = (const float*)d_in[6];
    const float* scale1  = (const float*)d_in[7];
    const float* offset1 = (const float*)d_in[8];
    const int*   erow    = (const int*)d_in[9];
    const int*   ecol    = (const int*)d_in[10];
    const float* eval    = (const float*)d_in[11];
    float* out = (float*)d_out;

    cudaFuncSetAttribute(gemm_fused_kernel,
                         cudaFuncAttributeMaxDynamicSharedMemorySize, GEMM_SMEM);

    // CSR build (independent of GEMM)
    zero_cnt_kernel<<<(N_NODES + 255) / 256, 256>>>();
    hist_kernel<<<(N_EDGES + 255) / 256, 256>>>(erow);
    scan_kernel<<<1, 1024>>>();
    scatter_kernel<<<(N_EDGES + 255) / 256, 256>>>(erow, ecol, eval);

    // GEMMs (produces out[:, :128] and g_Z)
    gemm_fused_kernel<<<(N_NODES + TM - 1) / TM, 256, GEMM_SMEM>>>(
        feat, W0, b0, scale0, offset0, W1, out);

    // fused SpMM + LN (produces out[:, 128:])
    spmm_ln_kernel<<<(N_NODES + 7) / 8, 256>>>(b1, scale1, offset1, out);
}

// round 4
// speedup vs baseline: 1.0462x; 1.0001x over previous
#include <cuda_runtime.h>
#include <cstdint>

#define N_NODES 50000
#define N_EDGES 800000
#define D_IN    256
#define D_OUT   128
#define EPSV    1e-9f

// Scratch (allocation-free rule: __device__ globals)
__device__ float g_Z [(size_t)N_NODES * D_OUT];   // Z = feat @ W1   [N, 128]
__device__ int   g_cnt[N_NODES];                  // per-row edge counts
__device__ int   g_rs [N_NODES + 1];              // CSR row starts
__device__ int   g_cur[N_NODES];                  // scatter cursors
__device__ int   g_scol[N_EDGES];                 // sorted cols
__device__ float g_sval[N_EDGES];                 // sorted vals

// ---------------- packed f32x2 helpers (Blackwell) ----------------
__device__ __forceinline__ unsigned long long pack2(float v) {
    unsigned long long r;
    asm("mov.b64 %0, {%1, %2};" : "=l"(r) : "f"(v), "f"(v));
    return r;
}
__device__ __forceinline__ void unpack2(unsigned long long v, float& lo, float& hi) {
    asm("mov.b64 {%0, %1}, %2;" : "=f"(lo), "=f"(hi) : "l"(v));
}
__device__ __forceinline__ void fma2(unsigned long long& d, unsigned long long a, unsigned long long b) {
    asm("fma.rn.f32x2 %0, %1, %2, %0;" : "+l"(d) : "l"(a), "l"(b));
}

// ---------------- CSR build ----------------
__global__ void zero_cnt_kernel() {
    int i = blockIdx.x * blockDim.x + threadIdx.x;
    if (i < N_NODES) g_cnt[i] = 0;
}

__global__ void hist_kernel(const int* __restrict__ erow) {
    int e = blockIdx.x * blockDim.x + threadIdx.x;
    if (e < N_EDGES) atomicAdd(&g_cnt[__ldg(erow + e)], 1);
}

// single-block exclusive scan over 50k counts -> g_rs, g_cur
__global__ void __launch_bounds__(1024) scan_kernel() {
    __shared__ int sums[1024];
    const int CH = (N_NODES + 1023) / 1024;  // 49
    int t = threadIdx.x;
    int base = t * CH;
    int s = 0;
    for (int i = 0; i < CH; ++i) {
        int idx = base + i;
        if (idx < N_NODES) s += g_cnt[idx];
    }
    sums[t] = s;
    __syncthreads();
    // Hillis-Steele inclusive scan
    for (int off = 1; off < 1024; off <<= 1) {
        int v = (t >= off) ? sums[t - off] : 0;
        __syncthreads();
        sums[t] += v;
        __syncthreads();
    }
    int run = sums[t] - s;   // exclusive prefix
    for (int i = 0; i < CH; ++i) {
        int idx = base + i;
        if (idx < N_NODES) {
            g_rs[idx]  = run;
            g_cur[idx] = run;
            run += g_cnt[idx];
        }
    }
    if (t == 1023) g_rs[N_NODES] = sums[1023];
}

__global__ void scatter_kernel(const int* __restrict__ erow, const int* __restrict__ ecol,
                               const float* __restrict__ eval) {
    int e = blockIdx.x * blockDim.x + threadIdx.x;
    if (e >= N_EDGES) return;
    int r = __ldg(erow + e);
    int pos = atomicAdd(&g_cur[r], 1);
    g_scol[pos] = __ldg(ecol + e);
    g_sval[pos] = __ldg(eval + e);
}

// ---------------- fused GEMM: out[:, :128] = LN(relu(feat@W0+b0)); g_Z = feat@W1 ----------------
#define TM 64
#define KC 64
#define XSTRIDE 68
#define GEMM_SMEM ((KC*256 + TM*XSTRIDE) * 4)   // 82944 B

__global__ void __launch_bounds__(256, 2)
gemm_fused_kernel(const float* __restrict__ feat,
                  const float* __restrict__ W0, const float* __restrict__ b0,
                  const float* __restrict__ scale0, const float* __restrict__ offset0,
                  const float* __restrict__ W1,
                  float* __restrict__ out)
{
    extern __shared__ float smem[];
    float* Ws = smem;                 // [KC][256]
    float* Xs = smem + KC * 256;      // [TM][XSTRIDE]

    const int tid  = threadIdx.x;
    const int warp = tid >> 5;
    const int lane = tid & 31;
    const int row0 = blockIdx.x * TM;

    unsigned long long acc[8][4];
#pragma unroll
    for (int r = 0; r < 8; ++r)
#pragma unroll
        for (int j = 0; j < 4; ++j) acc[r][j] = 0ull;

    for (int kc = 0; kc < D_IN / KC; ++kc) {
        for (int i = tid; i < (KC * 256) / 4; i += 256) {
            int k  = i >> 6;
            int n4 = (i & 63) * 4;
            int kg = kc * KC + k;
            float4 v;
            if (n4 < 128) v = *reinterpret_cast<const float4*>(W0 + (size_t)kg * 128 + n4);
            else          v = *reinterpret_cast<const float4*>(W1 + (size_t)kg * 128 + (n4 - 128));
            *reinterpret_cast<float4*>(&Ws[k * 256 + n4]) = v;
        }
        for (int i = tid; i < (TM * KC) / 4; i += 256) {
            int r  = i >> 4;
            int c4 = (i & 15) * 4;
            int grow = row0 + r;
            float4 v = make_float4(0.f, 0.f, 0.f, 0.f);
            if (grow < N_NODES)
                v = *reinterpret_cast<const float4*>(feat + (size_t)grow * D_IN + kc * KC + c4);
            *reinterpret_cast<float4*>(&Xs[r * XSTRIDE + c4]) = v;
        }
        __syncthreads();

        const float* xbase = Xs + (warp * 8) * XSTRIDE;
#pragma unroll 4
        for (int k = 0; k < KC; ++k) {
            const float* wrow = Ws + k * 256;
            unsigned long long w0 = *reinterpret_cast<const unsigned long long*>(wrow + 2 * lane);
            unsigned long long w1 = *reinterpret_cast<const unsigned long long*>(wrow + 64 + 2 * lane);
            unsigned long long w2 = *reinterpret_cast<const unsigned long long*>(wrow + 128 + 2 * lane);
            unsigned long long w3 = *reinterpret_cast<const unsigned long long*>(wrow + 192 + 2 * lane);
#pragma unroll
            for (int rr = 0; rr < 8; ++rr) {
                unsigned long long x2 = pack2(xbase[rr * XSTRIDE + k]);
                fma2(acc[rr][0], x2, w0);
                fma2(acc[rr][1], x2, w1);
                fma2(acc[rr][2], x2, w2);
                fma2(acc[rr][3], x2, w3);
            }
        }
        __syncthreads();
    }

    float2 bA = *reinterpret_cast<const float2*>(b0 + 2 * lane);
    float2 bB = *reinterpret_cast<const float2*>(b0 + 64 + 2 * lane);
    float2 sA = *reinterpret_cast<const float2*>(scale0 + 2 * lane);
    float2 sB = *reinterpret_cast<const float2*>(scale0 + 64 + 2 * lane);
    float2 oA = *reinterpret_cast<const float2*>(offset0 + 2 * lane);
    float2 oB = *reinterpret_cast<const float2*>(offset0 + 64 + 2 * lane);

#pragma unroll
    for (int rr = 0; rr < 8; ++rr) {
        int row = row0 + warp * 8 + rr;
        float a0, a1, a2, a3;
        unpack2(acc[rr][0], a0, a1);
        unpack2(acc[rr][1], a2, a3);
        a0 = fmaxf(a0 + bA.x, 0.f);
        a1 = fmaxf(a1 + bA.y, 0.f);
        a2 = fmaxf(a2 + bB.x, 0.f);
        a3 = fmaxf(a3 + bB.y, 0.f);
        float s = a0 + a1 + a2 + a3;
        float q = a0 * a0 + a1 * a1 + a2 * a2 + a3 * a3;
#pragma unroll
        for (int off = 16; off > 0; off >>= 1) {
            s += __shfl_xor_sync(0xffffffffu, s, off);
            q += __shfl_xor_sync(0xffffffffu, q, off);
        }
        float mean = s * (1.f / 128.f);
        float var  = q * (1.f / 128.f) - mean * mean;
        float inv  = rsqrtf(var + EPSV);
        if (row < N_NODES) {
            float2 w;
            w.x = (a0 - mean) * inv * sA.x + oA.x;
            w.y = (a1 - mean) * inv * sA.y + oA.y;
            *reinterpret_cast<float2*>(out + (size_t)row * 256 + 2 * lane) = w;
            w.x = (a2 - mean) * inv * sB.x + oB.x;
            w.y = (a3 - mean) * inv * sB.y + oB.y;
            *reinterpret_cast<float2*>(out + (size_t)row * 256 + 64 + 2 * lane) = w;
            *reinterpret_cast<unsigned long long*>(g_Z + (size_t)row * 128 + 2 * lane) = acc[rr][2];
            *reinterpret_cast<unsigned long long*>(g_Z + (size_t)row * 128 + 64 + 2 * lane) = acc[rr][3];
        }
    }
}

// ---------------- fused CSR SpMM + LN: out[:, 128:] = LN(relu((A@Z) + b1)) ----------------
// One warp per row; per-lane float4 accumulator (lane covers cols 4l..4l+3).
__global__ void __launch_bounds__(256)
spmm_ln_kernel(const float* __restrict__ b1, const float* __restrict__ scale1,
               const float* __restrict__ offset1, float* __restrict__ out)
{
    int row = blockIdx.x * 8 + (threadIdx.x >> 5);
    if (row >= N_NODES) return;
    int lane = threadIdx.x & 31;

    int start = __ldg(&g_rs[row]);
    int end   = __ldg(&g_rs[row + 1]);

    float4 acc = make_float4(0.f, 0.f, 0.f, 0.f);
    int e = start;
    for (; e + 1 < end; e += 2) {
        int   c0 = __ldg(g_scol + e);
        int   c1 = __ldg(g_scol + e + 1);
        float v0 = __ldg(g_sval + e);
        float v1 = __ldg(g_sval + e + 1);
        float4 z0 = *reinterpret_cast<const float4*>(g_Z + (size_t)c0 * 128 + lane * 4);
        float4 z1 = *reinterpret_cast<const float4*>(g_Z + (size_t)c1 * 128 + lane * 4);
        acc.x = fmaf(v0, z0.x, acc.x); acc.y = fmaf(v0, z0.y, acc.y);
        acc.z = fmaf(v0, z0.z, acc.z); acc.w = fmaf(v0, z0.w, acc.w);
        acc.x = fmaf(v1, z1.x, acc.x); acc.y = fmaf(v1, z1.y, acc.y);
        acc.z = fmaf(v1, z1.z, acc.z); acc.w = fmaf(v1, z1.w, acc.w);
    }
    if (e < end) {
        int   c0 = __ldg(g_scol + e);
        float v0 = __ldg(g_sval + e);
        float4 z0 = *reinterpret_cast<const float4*>(g_Z + (size_t)c0 * 128 + lane * 4);
        acc.x = fmaf(v0, z0.x, acc.x); acc.y = fmaf(v0, z0.y, acc.y);
        acc.z = fmaf(v0, z0.z, acc.z); acc.w = fmaf(v0, z0.w, acc.w);
    }

    float4 b = *reinterpret_cast<const float4*>(b1 + lane * 4);
    acc.x = fmaxf(acc.x + b.x, 0.f);
    acc.y = fmaxf(acc.y + b.y, 0.f);
    acc.z = fmaxf(acc.z + b.z, 0.f);
    acc.w = fmaxf(acc.w + b.w, 0.f);
    float s = acc.x + acc.y + acc.z + acc.w;
    float q = acc.x * acc.x + acc.y * acc.y + acc.z * acc.z + acc.w * acc.w;
#pragma unroll
    for (int off = 16; off > 0; off >>= 1) {
        s += __shfl_xor_sync(0xffffffffu, s, off);
        q += __shfl_xor_sync(0xffffffffu, q, off);
    }
    float mean = s * (1.f / 128.f);
    float var  = q * (1.f / 128.f) - mean * mean;
    float inv  = rsqrtf(var + EPSV);
    float4 sc = *reinterpret_cast<const float4*>(scale1 + lane * 4);
    float4 of = *reinterpret_cast<const float4*>(offset1 + lane * 4);
    float4 w;
    w.x = (acc.x - mean) * inv * sc.x + of.x;
    w.y = (acc.y - mean) * inv * sc.y + of.y;
    w.z = (acc.z - mean) * inv * sc.z + of.z;
    w.w = (acc.w - mean) * inv * sc.w + of.w;
    *reinterpret_cast<float4*>(out + (size_t)row * 256 + 128 + lane * 4) = w;
}

extern "C" void kernel_launch(void* const* d_in, const int* in_sizes, int n_in,
                              void* d_out, int out_size)
{
    const float* feat    = (const float*)d_in[0];
    const float* W0      = (const float*)d_in[1];
    const float* b0      = (const float*)d_in[2];
    const float* scale0  = (const float*)d_in[3];
    const float* offset0 = (const float*)d_in[4];
    const float* W1      = (const float*)d_in[5];
    const float* b1      = (const float*)d_in[6];
    const float* scale1  = (const float*)d_in[7];
    const float* offset1 = (const float*)d_in[8];
    const int*   erow    = (const int*)d_in[9];
    const int*   ecol    = (const int*)d_in[10];
    const float* eval    = (const float*)d_in[11];
    float* out = (float*)d_out;

    cudaFuncSetAttribute(gemm_fused_kernel,
                         cudaFuncAttributeMaxDynamicSharedMemorySize, GEMM_SMEM);

    // CSR build (independent of GEMM)
    zero_cnt_kernel<<<(N_NODES + 255) / 256, 256>>>();
    hist_kernel<<<(N_EDGES + 255) / 256, 256>>>(erow);
    scan_kernel<<<1, 1024>>>();
    scatter_kernel<<<(N_EDGES + 255) / 256, 256>>>(erow, ecol, eval);

    // GEMMs (produces out[:, :128] and g_Z)
    gemm_fused_kernel<<<(N_NODES + TM - 1) / TM, 256, GEMM_SMEM>>>(
        feat, W0, b0, scale0, offset0, W1, out);

    // fused SpMM + LN (produces out[:, 128:])
    spmm_ln_kernel<<<(N_NODES + 7) / 8, 256>>>(b1, scale1, offset1, out);
}